// round 1
// baseline (speedup 1.0000x reference)
#include <cuda_runtime.h>
#include <math.h>

// Problem constants
#define B_ROWS 65536
#define DIM    512
#define MAX_ITER 50
#define TOL 1e-4f

// GEMM tiling
#define BM 128
#define BN 128
#define BK 16
#define TM 8
#define TN 8
#define NTHREADS 256

// ---------------- device scratch (no cudaMalloc allowed) ----------------
__device__ float g_zA[(size_t)B_ROWS * DIM];   // ping
__device__ float g_zB[(size_t)B_ROWS * DIM];   // pong
__device__ float g_Wt[DIM * DIM];              // W^T (k-major)
__device__ float g_errsq[MAX_ITER + 2];        // per-step ||z_k - z_{k+1}||^2
__device__ int   g_done;                       // sticky convergence flag
__device__ int   g_final;                      // 0 -> g_zA holds result, 1 -> g_zB

// ---------------- kernels ----------------

__global__ void init_kernel() {
    int t = threadIdx.x;
    if (t == 0) { g_done = 0; g_final = 0; }
    if (t < MAX_ITER + 2) g_errsq[t] = 0.0f;
}

// Wt[k][n] = W[n][k]
__global__ void transpose_kernel(const float* __restrict__ W) {
    __shared__ float tile[32][33];
    int x = blockIdx.x * 32 + threadIdx.x;   // col of W
    int y = blockIdx.y * 32 + threadIdx.y;   // row of W
    #pragma unroll
    for (int j = 0; j < 32; j += 8)
        tile[threadIdx.y + j][threadIdx.x] = W[(size_t)(y + j) * DIM + x];
    __syncthreads();
    int x2 = blockIdx.y * 32 + threadIdx.x;
    int y2 = blockIdx.x * 32 + threadIdx.y;
    #pragma unroll
    for (int j = 0; j < 32; j += 8)
        g_Wt[(size_t)(y2 + j) * DIM + x2] = tile[threadIdx.x][threadIdx.y + j];
}

// step 1: z1 = tanh(x)  (z0 = 0)
__global__ void first_iter_kernel(const float* __restrict__ x) {
    size_t i = (size_t)blockIdx.x * blockDim.x + threadIdx.x;
    float4 v = ((const float4*)x)[i];
    v.x = tanhf(v.x); v.y = tanhf(v.y); v.z = tanhf(v.z); v.w = tanhf(v.w);
    ((float4*)g_zA)[i] = v;
}

// decide convergence after step `iter` completed
__global__ void check_kernel(int iter) {
    if (g_errsq[iter] < TOL * TOL) g_done = 1;
}

// One fixed-point step: dst = tanh(src @ W^T + x); accumulates ||dst - src||^2
__global__ __launch_bounds__(NTHREADS, 2)
void gemm_tanh_kernel(const float* __restrict__ src, float* __restrict__ dst,
                      const float* __restrict__ x, int iter, int dst_idx)
{
    if (g_done) return;

    __shared__ float As[BK][BM];
    __shared__ float Bs[BK][BN];

    const int tid = threadIdx.x;
    const int block_row = blockIdx.y;   // 0..511
    const int block_col = blockIdx.x;   // 0..3

    const float* A    = src + (size_t)block_row * BM * DIM;
    const float* Bmat = g_Wt + block_col * BN;

    // A tile loads: 128x16 floats = 2 float4 per thread
    const int aRow = tid / 4;           // 0..63 (+64)
    const int aCol = (tid % 4) * 4;     // 0,4,8,12
    // B tile loads: 16x128 floats = 2 float4 per thread
    const int bRow = tid / 32;          // 0..7 (+8)
    const int bCol = (tid % 32) * 4;

    const int ty = (tid / 16) * TM;     // row offset in output tile
    const int tx = (tid % 16) * TN;     // col offset in output tile

    float acc[TM][TN];
    #pragma unroll
    for (int i = 0; i < TM; ++i)
        #pragma unroll
        for (int j = 0; j < TN; ++j) acc[i][j] = 0.0f;

    float regM[TM], regN[TN];

    for (int kt = 0; kt < DIM; kt += BK) {
        #pragma unroll
        for (int r = 0; r < 2; ++r) {
            int row = aRow + r * 64;
            float4 v = *(const float4*)&A[(size_t)row * DIM + kt + aCol];
            As[aCol + 0][row] = v.x;
            As[aCol + 1][row] = v.y;
            As[aCol + 2][row] = v.z;
            As[aCol + 3][row] = v.w;
        }
        #pragma unroll
        for (int r = 0; r < 2; ++r) {
            int row = bRow + r * 8;
            *(float4*)&Bs[row][bCol] =
                *(const float4*)&Bmat[(size_t)(kt + row) * DIM + bCol];
        }
        __syncthreads();

        #pragma unroll
        for (int k = 0; k < BK; ++k) {
            #pragma unroll
            for (int i = 0; i < TM; ++i) regM[i] = As[k][ty + i];
            #pragma unroll
            for (int j = 0; j < TN; ++j) regN[j] = Bs[k][tx + j];
            #pragma unroll
            for (int i = 0; i < TM; ++i)
                #pragma unroll
                for (int j = 0; j < TN; ++j)
                    acc[i][j] = fmaf(regM[i], regN[j], acc[i][j]);
        }
        __syncthreads();
    }

    // Epilogue: z_next = tanh(acc + x); track squared diff vs z_prev (== src)
    float diffsq = 0.0f;
    const int row0 = block_row * BM + ty;
    const int col0 = block_col * BN + tx;
    #pragma unroll
    for (int i = 0; i < TM; ++i) {
        size_t off = (size_t)(row0 + i) * DIM + col0;
        #pragma unroll
        for (int j4 = 0; j4 < TN; j4 += 4) {
            float4 xv = *(const float4*)&x[off + j4];
            float4 zp = *(const float4*)&src[off + j4];
            float4 o;
            o.x = tanhf(acc[i][j4 + 0] + xv.x);
            o.y = tanhf(acc[i][j4 + 1] + xv.y);
            o.z = tanhf(acc[i][j4 + 2] + xv.z);
            o.w = tanhf(acc[i][j4 + 3] + xv.w);
            *(float4*)&dst[off + j4] = o;
            float d0 = o.x - zp.x, d1 = o.y - zp.y;
            float d2 = o.z - zp.z, d3 = o.w - zp.w;
            diffsq += d0 * d0 + d1 * d1 + d2 * d2 + d3 * d3;
        }
    }

    // block reduction of diffsq
    #pragma unroll
    for (int o = 16; o; o >>= 1)
        diffsq += __shfl_xor_sync(0xffffffffu, diffsq, o);
    __shared__ float red[NTHREADS / 32];
    if ((tid & 31) == 0) red[tid >> 5] = diffsq;
    __syncthreads();
    if (tid < (NTHREADS / 32)) {
        float v = red[tid];
        #pragma unroll
        for (int o = (NTHREADS / 64); o; o >>= 1)
            v += __shfl_xor_sync(0xffu, v, o);
        if (tid == 0) {
            atomicAdd(&g_errsq[iter], v);
            g_final = dst_idx;   // every block writes the same value
        }
    }
}

__global__ void copy_out_kernel(float* __restrict__ out) {
    const float* srcp = g_final ? g_zB : g_zA;
    size_t i = (size_t)blockIdx.x * blockDim.x + threadIdx.x;
    ((float4*)out)[i] = ((const float4*)srcp)[i];
}

// ---------------- host launcher ----------------
extern "C" void kernel_launch(void* const* d_in, const int* in_sizes, int n_in,
                              void* d_out, int out_size)
{
    const float* x;
    const float* W;
    if (n_in >= 2 && in_sizes[0] == DIM * DIM) {   // robust input-order detection
        W = (const float*)d_in[0];
        x = (const float*)d_in[1];
    } else {
        x = (const float*)d_in[0];
        W = (const float*)d_in[1];
    }
    float* out = (float*)d_out;

    float* zA = nullptr;
    float* zB = nullptr;
    cudaGetSymbolAddress((void**)&zA, g_zA);
    cudaGetSymbolAddress((void**)&zB, g_zB);
    float* bufs[2] = { zA, zB };

    init_kernel<<<1, 64>>>();
    transpose_kernel<<<dim3(16, 16), dim3(32, 8)>>>(W);

    // step 1: z1 = tanh(x) -> zA
    {
        const size_t n4 = (size_t)B_ROWS * DIM / 4;
        first_iter_kernel<<<(unsigned)(n4 / 256), 256>>>(x);
    }

    // steps 2..50
    dim3 grid(DIM / BN, B_ROWS / BM);   // (4, 512)
    for (int it = 2; it <= MAX_ITER; ++it) {
        if (it >= 3) check_kernel<<<1, 1>>>(it - 1);
        const float* s = bufs[it & 1];        // it=2 -> zA (holds z1)
        float*       d = bufs[(it & 1) ^ 1];  // it=2 -> zB
        gemm_tanh_kernel<<<grid, NTHREADS>>>(s, d, x, it, (it & 1) ^ 1);
    }

    // write final z into d_out
    {
        const size_t n4 = (size_t)B_ROWS * DIM / 4;
        copy_out_kernel<<<(unsigned)(n4 / 256), 256>>>(out);
    }
}

// round 3
// speedup vs baseline: 5.6141x; 5.6141x over previous
#include <cuda_runtime.h>
#include <cuda_fp16.h>
#include <cstdint>
#include <cstddef>

#define BATCH 65536
#define DIM   512
#define NSTEPS 50            // z_1 .. z_50 ; 49 GEMM steps
#define TILE_M 128
#define TILE_N 128
#define KB     32            // k-chunk
#define NCHUNK (DIM / KB)    // 16
#define NTHREADS 512
#define ROWSTRIDE 40         // halfs per smem row (80B, ldmatrix conflict-free)

// ---------------- device scratch ----------------
__device__ __half g_z0[(size_t)BATCH * DIM];
__device__ __half g_z1[(size_t)BATCH * DIM];
__device__ __half g_Wh[DIM * DIM];

// ---------------- helpers ----------------
__device__ __forceinline__ uint32_t smem_u32(const void* p) {
    uint32_t a;
    asm("{ .reg .u64 t; cvta.to.shared.u64 t, %1; cvt.u32.u64 %0, t; }" : "=r"(a) : "l"(p));
    return a;
}
__device__ __forceinline__ void cp16(uint32_t s, const void* g) {
    asm volatile("cp.async.cg.shared.global [%0], [%1], 16;" :: "r"(s), "l"(g));
}
__device__ __forceinline__ void ldsm_x4(uint32_t& r0, uint32_t& r1, uint32_t& r2,
                                        uint32_t& r3, uint32_t addr) {
    asm volatile("ldmatrix.sync.aligned.m8n8.x4.shared.b16 {%0,%1,%2,%3}, [%4];"
                 : "=r"(r0), "=r"(r1), "=r"(r2), "=r"(r3) : "r"(addr));
}
__device__ __forceinline__ void mma16816(float* d, const uint32_t* a,
                                         uint32_t b0, uint32_t b1) {
    asm volatile(
        "mma.sync.aligned.m16n8k16.row.col.f32.f16.f16.f32 "
        "{%0,%1,%2,%3}, {%4,%5,%6,%7}, {%8,%9}, {%0,%1,%2,%3};"
        : "+f"(d[0]), "+f"(d[1]), "+f"(d[2]), "+f"(d[3])
        : "r"(a[0]), "r"(a[1]), "r"(a[2]), "r"(a[3]), "r"(b0), "r"(b1));
}
// fast tanh: 1 - 2/(exp(2v)+1)
__device__ __forceinline__ float tanh_fast(float v) {
    float e = __expf(2.0f * v);
    return 1.0f - __fdividef(2.0f, e + 1.0f);
}

// ---------------- setup kernels ----------------
__global__ void convert_w_kernel(const float* __restrict__ W) {
    size_t i = ((size_t)blockIdx.x * blockDim.x + threadIdx.x) * 4;
    float4 v = *(const float4*)(W + i);
    __half2 a = __floats2half2_rn(v.x, v.y);
    __half2 b = __floats2half2_rn(v.z, v.w);
    uint2 u;
    u.x = *(uint32_t*)&a;
    u.y = *(uint32_t*)&b;
    *(uint2*)(g_Wh + i) = u;
}

__global__ void first_iter_kernel(const float* __restrict__ x) {
    size_t i = ((size_t)blockIdx.x * blockDim.x + threadIdx.x) * 4;
    float4 v = *(const float4*)(x + i);
    __half2 a = __floats2half2_rn(tanh_fast(v.x), tanh_fast(v.y));
    __half2 b = __floats2half2_rn(tanh_fast(v.z), tanh_fast(v.w));
    uint2 u;
    u.x = *(uint32_t*)&a;
    u.y = *(uint32_t*)&b;
    *(uint2*)(g_z0 + i) = u;
}

// ---------------- main step: zdst = tanh(zsrc @ W^T + x) ----------------
__global__ void __launch_bounds__(NTHREADS)
gemm_tanh_step(const __half* __restrict__ zsrc, __half* __restrict__ zdst,
               const float* __restrict__ x, float* __restrict__ dout,
               int is_final)
{
    __shared__ __half As[2][TILE_M * ROWSTRIDE];
    __shared__ __half Bs[2][TILE_N * ROWSTRIDE];

    const int tid    = threadIdx.x;
    const int lane   = tid & 31;
    const int wid    = tid >> 5;
    const int warp_m = wid & 3;          // 4 warps over M (32 rows each)
    const int warp_n = wid >> 2;         // 4 warps over N (32 cols each)
    const int m0     = blockIdx.y * TILE_M;
    const int n0     = blockIdx.x * TILE_N;

    const uint32_t sA[2] = { smem_u32(As[0]), smem_u32(As[1]) };
    const uint32_t sB[2] = { smem_u32(Bs[0]), smem_u32(Bs[1]) };

    // per-thread load slots (512 threads cover 128 rows x 4 x 16B exactly)
    const int ldRow = tid >> 2;
    const int ldSeg = (tid & 3) * 8;                      // halfs
    const uint32_t ldOff = (uint32_t)(ldRow * ROWSTRIDE + ldSeg) * 2;
    const __half* gA = zsrc + (size_t)(m0 + ldRow) * DIM + ldSeg;
    const __half* gB = g_Wh + (size_t)(n0 + ldRow) * DIM + ldSeg;

    // ldmatrix lane offsets (halfs), relative to (warp tile, kstep)
    // A: row = warp_m*32 + mf*16 + (lane&15), col = ((lane>>4)<<3)
    const uint32_t aLane = (uint32_t)((warp_m * 32 + (lane & 15)) * ROWSTRIDE +
                                      ((lane >> 4) << 3)) * 2;
    // B: row(n) = warp_n*32 + bf*16 + ((lane>>4)<<3) + (lane&7), col = ((lane>>3)&1)*8
    const uint32_t bLane = (uint32_t)((warp_n * 32 + ((lane >> 4) << 3) + (lane & 7)) *
                                      ROWSTRIDE + (((lane >> 3) & 1) << 3)) * 2;

    float acc[2][4][4];
    #pragma unroll
    for (int i = 0; i < 2; ++i)
        #pragma unroll
        for (int j = 0; j < 4; ++j)
            #pragma unroll
            for (int k = 0; k < 4; ++k) acc[i][j][k] = 0.0f;

    auto load_chunk = [&](int c) {
        const int s = c & 1;
        const int kt = c * KB;
        cp16(sA[s] + ldOff, gA + kt);
        cp16(sB[s] + ldOff, gB + kt);
        asm volatile("cp.async.commit_group;" ::: "memory");
    };

    load_chunk(0);

    for (int c = 0; c < NCHUNK; ++c) {
        const int s = c & 1;
        asm volatile("cp.async.wait_group 0;" ::: "memory");
        __syncthreads();
        if (c + 1 < NCHUNK) load_chunk(c + 1);

        #pragma unroll
        for (int kstep = 0; kstep < 2; ++kstep) {
            const uint32_t kOff = (uint32_t)(kstep * 16) * 2;
            uint32_t a[2][4], b[2][4];
            #pragma unroll
            for (int mf = 0; mf < 2; ++mf)
                ldsm_x4(a[mf][0], a[mf][1], a[mf][2], a[mf][3],
                        sA[s] + aLane + kOff + (uint32_t)(mf * 16 * ROWSTRIDE) * 2);
            #pragma unroll
            for (int bf = 0; bf < 2; ++bf)
                ldsm_x4(b[bf][0], b[bf][1], b[bf][2], b[bf][3],
                        sB[s] + bLane + kOff + (uint32_t)(bf * 16 * ROWSTRIDE) * 2);
            #pragma unroll
            for (int mf = 0; mf < 2; ++mf)
                #pragma unroll
                for (int nf = 0; nf < 4; ++nf)
                    mma16816(acc[mf][nf], a[mf],
                             b[nf >> 1][(nf & 1) * 2], b[nf >> 1][(nf & 1) * 2 + 1]);
        }
        __syncthreads();
    }

    // ---- epilogue: + x, tanh, store ----
    const int er = lane >> 2;            // 0..7
    const int ec = (lane & 3) * 2;       // 0,2,4,6
    #pragma unroll
    for (int mf = 0; mf < 2; ++mf) {
        #pragma unroll
        for (int nf = 0; nf < 4; ++nf) {
            const int n = n0 + warp_n * 32 + nf * 8 + ec;
            #pragma unroll
            for (int half = 0; half < 2; ++half) {     // rows r and r+8
                const int m = m0 + warp_m * 32 + mf * 16 + er + half * 8;
                const size_t go = (size_t)m * DIM + n;
                float2 xv = *(const float2*)(x + go);
                float v0 = tanh_fast(acc[mf][nf][half * 2 + 0] + xv.x);
                float v1 = tanh_fast(acc[mf][nf][half * 2 + 1] + xv.y);
                if (is_final) {
                    *(float2*)(dout + go) = make_float2(v0, v1);
                } else {
                    __half2 h = __floats2half2_rn(v0, v1);
                    *(uint32_t*)(zdst + go) = *(uint32_t*)&h;
                }
            }
        }
    }
}

// ---------------- host launcher ----------------
extern "C" void kernel_launch(void* const* d_in, const int* in_sizes, int n_in,
                              void* d_out, int out_size)
{
    const float *x, *W;
    if (n_in >= 2 && in_sizes[0] == DIM * DIM) {
        W = (const float*)d_in[0];
        x = (const float*)d_in[1];
    } else {
        x = (const float*)d_in[0];
        W = (const float*)d_in[1];
    }
    float* dout = (float*)d_out;

    __half* z0 = nullptr;
    __half* z1 = nullptr;
    cudaGetSymbolAddress((void**)&z0, g_z0);
    cudaGetSymbolAddress((void**)&z1, g_z1);
    __half* bufs[2] = { z0, z1 };

    convert_w_kernel<<<DIM * DIM / (4 * 256), 256>>>(W);
    first_iter_kernel<<<(unsigned)(((size_t)BATCH * DIM) / (4 * 256)), 256>>>(x);

    dim3 grid(DIM / TILE_N, BATCH / TILE_M);   // (4, 512)
    int cur = 0;
    for (int k = 2; k <= NSTEPS; ++k) {
        int fin = (k == NSTEPS) ? 1 : 0;
        gemm_tanh_step<<<grid, NTHREADS>>>(bufs[cur], bufs[cur ^ 1], x, dout, fin);
        cur ^= 1;
    }
}